// round 12
// baseline (speedup 1.0000x reference)
#include <cuda_runtime.h>
#include <stdint.h>

// Problem constants
#define N_V   16384
#define N_E   8192
#define CIN   128
#define COUT  64
#define LOG_M 13

// Extraction config (R1-proven, DO NOT TOUCH)
#define EBLOCKS  2048
#define ETHREADS 256
#define CAPB     512                       // COO slots per block (mean ~328, 10 sigma safe)
#define NTOT     (EBLOCKS*ETHREADS)        // 524288 threads
#define EITER    64                        // (N_V*N_E/4)/NTOT exactly

// bucket config: 4 slots/thread, vertex side + edge side independent
#define BUCKB4   ((EBLOCKS*CAPB)/(256*4))  // 1024 blocks per side

// ---------------- scratch (device globals; no allocation) ----------------
__device__ int            g_deg_v[N_V];
__device__ int            g_deg_e[N_E];
__device__ int            g_cur_v[N_V];
__device__ int            g_cur_e[N_E];
__device__ int            g_off_v[N_V + 1];
__device__ int            g_off_e[N_E + 1];
__device__ int            g_blk_cnt[EBLOCKS];
__device__ unsigned int   g_coo[EBLOCKS * CAPB];     // packed (i<<13)|j
__device__ unsigned short g_adj_v[EBLOCKS * CAPB];   // CSR by vertex: edge ids
__device__ unsigned short g_adj_e[EBLOCKS * CAPB];   // CSC by edge: vertex ids
__device__ float          g_dv[N_V];
__device__ float          g_de[N_E];
__device__ float          g_Z[N_V * COUT];           // X W^T + b   (dv folded in k_edge)
__device__ float          g_Y2[N_E * COUT];          // de * (H^T @ dv.Z)

// ---------------- kernel 1: extract (EXACT R1/R9 shape; REDG atomics) ----------
__global__ void k_extract(const float* __restrict__ H) {
    __shared__ int s_cnt;
    if (threadIdx.x == 0) s_cnt = 0;
    __syncthreads();

    const uint4* __restrict__ H4 = (const uint4*)H;
    int tid = blockIdx.x * ETHREADS + threadIdx.x;
    unsigned cooBase = blockIdx.x * CAPB;

#pragma unroll 4
    for (int it = 0; it < EITER; it++) {
        int v = tid + it * NTOT;
        uint4 h = H4[v];
        if ((h.x | h.y | h.z | h.w) == 0u) continue;   // ~98% of vectors
        int e = v * 4;
#pragma unroll
        for (int c = 0; c < 4; c++) {
            unsigned hv = (c == 0) ? h.x : (c == 1) ? h.y : (c == 2) ? h.z : h.w;
            if (hv) {
                int ee = e + c;
                int i = ee >> LOG_M;
                int j = ee & (N_E - 1);
                atomicAdd(&g_deg_v[i], 1);             // return unused -> REDG
                atomicAdd(&g_deg_e[j], 1);             // return unused -> REDG
                int p = atomicAdd(&s_cnt, 1);          // shared atomic: cheap
                if (p < CAPB)
                    g_coo[cooBase + p] = ((unsigned)i << LOG_M) | (unsigned)j;
            }
        }
    }
    __syncthreads();
    if (threadIdx.x == 0)
        g_blk_cnt[blockIdx.x] = (s_cnt < CAPB) ? s_cnt : CAPB;
}

// ---------------- kernel 2: scan + scales (R9 shape, 1024 threads) -------------
__device__ void scan_scale_1024(int n, const int* __restrict__ deg,
                                int* __restrict__ off, float* __restrict__ sc,
                                bool isV) {
    __shared__ int part[1024];
    int tid = threadIdx.x;
    int per = n >> 10;
    int base = tid * per;
    int s = 0;
    for (int k = 0; k < per; k++) s += deg[base + k];
    part[tid] = s;
    __syncthreads();
    for (int d = 1; d < 1024; d <<= 1) {
        int v = (tid >= d) ? part[tid - d] : 0;
        __syncthreads();
        part[tid] += v;
        __syncthreads();
    }
    int pre = tid ? part[tid - 1] : 0;
    for (int k = 0; k < per; k++) {
        int d = deg[base + k];
        off[base + k] = pre;
        pre += d;
        sc[base + k] = (d > 0) ? (isV ? rsqrtf((float)d) : 1.0f / (float)d) : 0.0f;
    }
    if (tid == 1023) off[n] = pre;
}

__global__ void k_scan_scales() {
    if (blockIdx.x == 0) scan_scale_1024(N_V, g_deg_v, g_off_v, g_dv, true);
    else                 scan_scale_1024(N_E, g_deg_e, g_off_e, g_de, false);
}

// ---------------- kernel 3: bucket, 4 slots/thread, v-side/e-side split ---------
// Blocks [0,1024): vertex side (1 atomic chain); [1024,2048): edge side.
// Each thread: one uint4 COO load + 4 INDEPENDENT atomics batched -> MLP 4.
__global__ void k_bucket() {
    int bx = blockIdx.x;
    bool vside = bx < BUCKB4;
    int idx4 = (vside ? bx : bx - BUCKB4) * 256 + threadIdx.x;   // 0..262143
    uint4 q = ((const uint4*)g_coo)[idx4];
    int blk = idx4 >> 7;                       // (idx4*4)>>9
    int cnt = g_blk_cnt[blk];
    int loc = (idx4 << 2) & (CAPB - 1);
    unsigned pk[4] = {q.x, q.y, q.z, q.w};
    if (vside) {
        int slot[4];
#pragma unroll
        for (int u = 0; u < 4; u++)
            if (loc + u < cnt) slot[u] = atomicAdd(&g_cur_v[pk[u] >> LOG_M], 1);
#pragma unroll
        for (int u = 0; u < 4; u++)
            if (loc + u < cnt) {
                int i = pk[u] >> LOG_M;
                g_adj_v[g_off_v[i] + slot[u]] = (unsigned short)(pk[u] & (N_E - 1));
            }
    } else {
        int slot[4];
#pragma unroll
        for (int u = 0; u < 4; u++)
            if (loc + u < cnt) slot[u] = atomicAdd(&g_cur_e[pk[u] & (N_E - 1)], 1);
#pragma unroll
        for (int u = 0; u < 4; u++)
            if (loc + u < cnt) {
                int j = pk[u] & (N_E - 1);
                g_adj_e[g_off_e[j] + slot[u]] = (unsigned short)(pk[u] >> LOG_M);
            }
    }
}

// ---------------- kernel 4 (forked stream): GEMM  Z = X W^T + b ----------------
// R9-proven shape; runs concurrent with scan+bucket (low-issue window).
__global__ void k_gemm(const float* __restrict__ X,
                       const float* __restrict__ W,
                       const float* __restrict__ b) {
    __shared__ float Xs[32 * 128];   // 16 KB
    __shared__ float Ws[128 * 64];   // 32 KB  [k][c^swz]
    int tid = threadIdx.x;           // 128 threads
    int row0 = blockIdx.x * 32;

    const float4* __restrict__ Xg = (const float4*)(X + row0 * CIN);
    float4* Xs4 = (float4*)Xs;
#pragma unroll
    for (int t = 0; t < 8; t++) Xs4[tid + t * 128] = Xg[tid + t * 128];

#pragma unroll
    for (int t = 0; t < 64; t++) {
        int idx = tid + t * 128;               // 0..8191, linear over W
        int c = idx >> 7, k = idx & 127;
        Ws[k * 64 + (c ^ (k & 28))] = W[idx];
    }
    __syncthreads();

    int cx = (tid & 15) * 4;
    int ry = (tid >> 4) * 4;
    float acc[4][4] = {};

#pragma unroll
    for (int k = 0; k < 128; k += 4) {
        int swz = k & 28;
        float4 wv[4], xv[4];
#pragma unroll
        for (int u = 0; u < 4; u++) wv[u] = *(const float4*)&Ws[(k + u) * 64 + (cx ^ swz)];
#pragma unroll
        for (int r = 0; r < 4; r++) xv[r] = *(const float4*)&Xs[(ry + r) * 128 + k];
#pragma unroll
        for (int r = 0; r < 4; r++) {
            acc[r][0] += xv[r].x * wv[0].x + xv[r].y * wv[1].x + xv[r].z * wv[2].x + xv[r].w * wv[3].x;
            acc[r][1] += xv[r].x * wv[0].y + xv[r].y * wv[1].y + xv[r].z * wv[2].y + xv[r].w * wv[3].y;
            acc[r][2] += xv[r].x * wv[0].z + xv[r].y * wv[1].z + xv[r].z * wv[2].z + xv[r].w * wv[3].z;
            acc[r][3] += xv[r].x * wv[0].w + xv[r].y * wv[1].w + xv[r].z * wv[2].w + xv[r].w * wv[3].w;
        }
    }

    float b0 = b[cx], b1 = b[cx + 1], b2 = b[cx + 2], b3 = b[cx + 3];
#pragma unroll
    for (int r = 0; r < 4; r++) {
        int i = row0 + ry + r;
        float4 o;
        o.x = acc[r][0] + b0;
        o.y = acc[r][1] + b1;
        o.z = acc[r][2] + b2;
        o.w = acc[r][3] + b3;
        *(float4*)&g_Z[i * COUT + cx] = o;
    }
}

// ---------------- kernel 5: Y2[j] = de_j * sum dv_i * Z[i]  (R8-measured shape) --
__global__ void k_edge() {
    int w = (blockIdx.x * blockDim.x + threadIdx.x) >> 5;
    int lane = threadIdx.x & 31;
    if (w >= N_E) return;
    int t = g_off_e[w], end = g_off_e[w + 1];
    float a0 = 0.f, a1 = 0.f;
    for (; t + 4 <= end; t += 4) {
        int i0 = g_adj_e[t];
        int i1 = g_adj_e[t + 1];
        int i2 = g_adj_e[t + 2];
        int i3 = g_adj_e[t + 3];
        float s0 = g_dv[i0], s1 = g_dv[i1], s2 = g_dv[i2], s3 = g_dv[i3];
        float z00 = g_Z[i0 * COUT + lane], z01 = g_Z[i0 * COUT + lane + 32];
        float z10 = g_Z[i1 * COUT + lane], z11 = g_Z[i1 * COUT + lane + 32];
        float z20 = g_Z[i2 * COUT + lane], z21 = g_Z[i2 * COUT + lane + 32];
        float z30 = g_Z[i3 * COUT + lane], z31 = g_Z[i3 * COUT + lane + 32];
        a0 += (s0 * z00 + s1 * z10) + (s2 * z20 + s3 * z30);
        a1 += (s0 * z01 + s1 * z11) + (s2 * z21 + s3 * z31);
    }
    for (; t < end; t++) {
        int i0 = g_adj_e[t];
        float s0 = g_dv[i0];
        a0 += s0 * g_Z[i0 * COUT + lane];
        a1 += s0 * g_Z[i0 * COUT + lane + 32];
    }
    float de = g_de[w];
    g_Y2[w * COUT + lane]      = a0 * de;
    g_Y2[w * COUT + lane + 32] = a1 * de;
}

// ---------------- kernel 6: out = relu(dv .* (H @ Y2)) + counter reset ----------
__global__ void k_vertex(float* __restrict__ out) {
    int gt = blockIdx.x * blockDim.x + threadIdx.x;
    int w = gt >> 5;
    int lane = threadIdx.x & 31;
    if (w < N_V) {
        int t = g_off_v[w], end = g_off_v[w + 1];
        float a0 = 0.f, a1 = 0.f;
        for (; t + 4 <= end; t += 4) {
            int j0 = g_adj_v[t];
            int j1 = g_adj_v[t + 1];
            int j2 = g_adj_v[t + 2];
            int j3 = g_adj_v[t + 3];
            float y00 = g_Y2[j0 * COUT + lane], y01 = g_Y2[j0 * COUT + lane + 32];
            float y10 = g_Y2[j1 * COUT + lane], y11 = g_Y2[j1 * COUT + lane + 32];
            float y20 = g_Y2[j2 * COUT + lane], y21 = g_Y2[j2 * COUT + lane + 32];
            float y30 = g_Y2[j3 * COUT + lane], y31 = g_Y2[j3 * COUT + lane + 32];
            a0 += (y00 + y10) + (y20 + y30);
            a1 += (y01 + y11) + (y21 + y31);
        }
        for (; t < end; t++) {
            int j0 = g_adj_v[t];
            a0 += g_Y2[j0 * COUT + lane];
            a1 += g_Y2[j0 * COUT + lane + 32];
        }
        float dv = g_dv[w];
        float o0 = dv * a0;
        float o1 = dv * a1;
        out[w * COUT + lane]      = o0 > 0.f ? o0 : 0.f;
        out[w * COUT + lane + 32] = o1 > 0.f ? o1 : 0.f;
    }
    // tail: re-zero counters for the NEXT launch (stream-ordered; launch 0
    // covered by static zero-init of __device__ globals).
    if (gt < N_V) { g_deg_v[gt] = 0; g_cur_v[gt] = 0; }
    if (gt < N_E) { g_deg_e[gt] = 0; g_cur_e[gt] = 0; }
}

// ------ launch: extract -> [scan -> bucket || gemm] -> edge -> vertex ------
static cudaStream_t s2 = nullptr;
static cudaEvent_t  evFork = nullptr, evJoin = nullptr;

extern "C" void kernel_launch(void* const* d_in, const int* in_sizes, int n_in,
                              void* d_out, int out_size) {
    const float* X = (const float*)d_in[0];   // (16384, 128)
    const float* H = (const float*)d_in[1];   // (16384, 8192)
    const float* W = (const float*)d_in[2];   // (64, 128)
    const float* b = (const float*)d_in[3];   // (64,)
    float* out = (float*)d_out;               // (16384, 64)

    if (s2 == nullptr) {                      // one-time host init (first call is
        cudaStreamCreateWithFlags(&s2, cudaStreamNonBlocking);     // the uncaptured
        cudaEventCreateWithFlags(&evFork, cudaEventDisableTiming); // correctness run)
        cudaEventCreateWithFlags(&evJoin, cudaEventDisableTiming);
    }

    k_extract<<<EBLOCKS, ETHREADS>>>(H);

    // fork AFTER extract: gemm overlaps the low-issue scan+bucket window
    cudaEventRecord(evFork, 0);
    cudaStreamWaitEvent(s2, evFork, 0);
    k_gemm<<<N_V / 32, 128, 0, s2>>>(X, W, b);

    k_scan_scales<<<2, 1024>>>();
    k_bucket     <<<2 * BUCKB4, 256>>>();

    // join: k_edge needs Z (s2) and adjacency (main)
    cudaEventRecord(evJoin, s2);
    cudaStreamWaitEvent(0, evJoin, 0);

    k_edge  <<<(N_E * 32) / 256, 256>>>();
    k_vertex<<<(N_V * 32) / 256, 256>>>(out);
}

// round 14
// speedup vs baseline: 1.0968x; 1.0968x over previous
#include <cuda_runtime.h>
#include <stdint.h>

// Problem constants
#define N_V   16384
#define N_E   8192
#define CIN   128
#define COUT  64
#define LOG_M 13

// Extraction config (R1 grid/caps; inner loop re-batched for MLP 8)
#define EBLOCKS  2048
#define ETHREADS 256
#define CAPB     512                       // COO slots per block (mean ~328, 10 sigma safe)
#define NTOT     (EBLOCKS*ETHREADS)        // 524288 threads
#define EITER    64                        // (N_V*N_E/4)/NTOT exactly

// ---------------- scratch (device globals; no allocation) ----------------
__device__ int            g_deg_v[N_V];
__device__ int            g_deg_e[N_E];
__device__ int            g_cur_v[N_V];
__device__ int            g_cur_e[N_E];
__device__ int            g_off_v[N_V + 1];
__device__ int            g_off_e[N_E + 1];
__device__ int            g_blk_cnt[EBLOCKS];
__device__ unsigned int   g_coo[EBLOCKS * CAPB];     // packed (i<<13)|j
__device__ unsigned short g_adj_v[EBLOCKS * CAPB];   // CSR by vertex: edge ids
__device__ unsigned short g_adj_e[EBLOCKS * CAPB];   // CSC by edge: vertex ids
__device__ float          g_dv[N_V];
__device__ float          g_de[N_E];
__device__ float          g_Z[N_V * COUT];           // X W^T + b   (dv folded in k_edge)
__device__ float          g_Y2[N_E * COUT];          // de * (H^T @ dv.Z)

// ---------------- kernel 1: extract, 8-deep explicit load batches ----------------
__device__ __forceinline__ void proc4(uint4 h, int v, int* s_cnt, unsigned cooBase) {
    if ((h.x | h.y | h.z | h.w) == 0u) return;         // ~98% of vectors
    int e = v * 4;
#pragma unroll
    for (int c = 0; c < 4; c++) {
        unsigned hv = (c == 0) ? h.x : (c == 1) ? h.y : (c == 2) ? h.z : h.w;
        if (hv) {
            int ee = e + c;
            int i = ee >> LOG_M;
            int j = ee & (N_E - 1);
            atomicAdd(&g_deg_v[i], 1);                 // return unused -> REDG
            atomicAdd(&g_deg_e[j], 1);                 // return unused -> REDG
            int p = atomicAdd(s_cnt, 1);               // shared atomic: cheap
            if (p < CAPB)
                g_coo[cooBase + p] = ((unsigned)i << LOG_M) | (unsigned)j;
        }
    }
}

__global__ void k_extract(const float* __restrict__ H) {
    __shared__ int s_cnt;
    if (threadIdx.x == 0) s_cnt = 0;
    __syncthreads();

    const uint4* __restrict__ H4 = (const uint4*)H;
    int tid = blockIdx.x * ETHREADS + threadIdx.x;
    unsigned cooBase = blockIdx.x * CAPB;

    for (int it = 0; it < EITER / 8; it++) {           // 8 batches of 8
        int v0 = tid + (it * 8) * NTOT;
        uint4 r[8];
#pragma unroll
        for (int u = 0; u < 8; u++) r[u] = H4[v0 + u * NTOT];
#pragma unroll
        for (int u = 0; u < 8; u++) proc4(r[u], v0 + u * NTOT, &s_cnt, cooBase);
    }
    __syncthreads();
    if (threadIdx.x == 0)
        g_blk_cnt[blockIdx.x] = (s_cnt < CAPB) ? s_cnt : CAPB;
}

// ---------------- kernel 2: scan + scales (R9 shape, 1024 threads) -------------
__device__ void scan_scale_1024(int n, const int* __restrict__ deg,
                                int* __restrict__ off, float* __restrict__ sc,
                                bool isV) {
    __shared__ int part[1024];
    int tid = threadIdx.x;
    int per = n >> 10;
    int base = tid * per;
    int s = 0;
    for (int k = 0; k < per; k++) s += deg[base + k];
    part[tid] = s;
    __syncthreads();
    for (int d = 1; d < 1024; d <<= 1) {
        int v = (tid >= d) ? part[tid - d] : 0;
        __syncthreads();
        part[tid] += v;
        __syncthreads();
    }
    int pre = tid ? part[tid - 1] : 0;
    for (int k = 0; k < per; k++) {
        int d = deg[base + k];
        off[base + k] = pre;
        pre += d;
        sc[base + k] = (d > 0) ? (isV ? rsqrtf((float)d) : 1.0f / (float)d) : 0.0f;
    }
    if (tid == 1023) off[n] = pre;
}

__global__ void k_scan_scales() {
    if (blockIdx.x == 0) scan_scale_1024(N_V, g_deg_v, g_off_v, g_dv, true);
    else                 scan_scale_1024(N_E, g_deg_e, g_off_e, g_de, false);
}

// ---------------- kernel 3: bucket (REVERTED to R9/R11 measured shape) ----------
__global__ void k_bucket() {
    int idx = blockIdx.x * blockDim.x + threadIdx.x;   // over EBLOCKS*CAPB slots
    int blk = idx >> 9;                                // CAPB = 512
    int loc = idx & (CAPB - 1);
    if (loc >= g_blk_cnt[blk]) return;
    unsigned p = g_coo[idx];
    int i = p >> LOG_M;
    int j = p & (N_E - 1);
    int pv = atomicAdd(&g_cur_v[i], 1);
    g_adj_v[g_off_v[i] + pv] = (unsigned short)j;
    int pe = atomicAdd(&g_cur_e[j], 1);
    g_adj_e[g_off_e[j] + pe] = (unsigned short)i;
}

// ---------------- kernel 4 (forked stream): GEMM  Z = X W^T + b ----------------
// R9-proven shape; runs concurrent with scan+bucket (low-issue window).
__global__ void k_gemm(const float* __restrict__ X,
                       const float* __restrict__ W,
                       const float* __restrict__ b) {
    __shared__ float Xs[32 * 128];   // 16 KB
    __shared__ float Ws[128 * 64];   // 32 KB  [k][c^swz]
    int tid = threadIdx.x;           // 128 threads
    int row0 = blockIdx.x * 32;

    const float4* __restrict__ Xg = (const float4*)(X + row0 * CIN);
    float4* Xs4 = (float4*)Xs;
#pragma unroll
    for (int t = 0; t < 8; t++) Xs4[tid + t * 128] = Xg[tid + t * 128];

#pragma unroll
    for (int t = 0; t < 64; t++) {
        int idx = tid + t * 128;               // 0..8191, linear over W
        int c = idx >> 7, k = idx & 127;
        Ws[k * 64 + (c ^ (k & 28))] = W[idx];
    }
    __syncthreads();

    int cx = (tid & 15) * 4;
    int ry = (tid >> 4) * 4;
    float acc[4][4] = {};

#pragma unroll
    for (int k = 0; k < 128; k += 4) {
        int swz = k & 28;
        float4 wv[4], xv[4];
#pragma unroll
        for (int u = 0; u < 4; u++) wv[u] = *(const float4*)&Ws[(k + u) * 64 + (cx ^ swz)];
#pragma unroll
        for (int r = 0; r < 4; r++) xv[r] = *(const float4*)&Xs[(ry + r) * 128 + k];
#pragma unroll
        for (int r = 0; r < 4; r++) {
            acc[r][0] += xv[r].x * wv[0].x + xv[r].y * wv[1].x + xv[r].z * wv[2].x + xv[r].w * wv[3].x;
            acc[r][1] += xv[r].x * wv[0].y + xv[r].y * wv[1].y + xv[r].z * wv[2].y + xv[r].w * wv[3].y;
            acc[r][2] += xv[r].x * wv[0].z + xv[r].y * wv[1].z + xv[r].z * wv[2].z + xv[r].w * wv[3].z;
            acc[r][3] += xv[r].x * wv[0].w + xv[r].y * wv[1].w + xv[r].z * wv[2].w + xv[r].w * wv[3].w;
        }
    }

    float b0 = b[cx], b1 = b[cx + 1], b2 = b[cx + 2], b3 = b[cx + 3];
#pragma unroll
    for (int r = 0; r < 4; r++) {
        int i = row0 + ry + r;
        float4 o;
        o.x = acc[r][0] + b0;
        o.y = acc[r][1] + b1;
        o.z = acc[r][2] + b2;
        o.w = acc[r][3] + b3;
        *(float4*)&g_Z[i * COUT + cx] = o;
    }
}

// ---------------- kernel 5: Y2[j] = de_j * sum dv_i * Z[i]  (R8-measured shape) --
__global__ void k_edge() {
    int w = (blockIdx.x * blockDim.x + threadIdx.x) >> 5;
    int lane = threadIdx.x & 31;
    if (w >= N_E) return;
    int t = g_off_e[w], end = g_off_e[w + 1];
    float a0 = 0.f, a1 = 0.f;
    for (; t + 4 <= end; t += 4) {
        int i0 = g_adj_e[t];
        int i1 = g_adj_e[t + 1];
        int i2 = g_adj_e[t + 2];
        int i3 = g_adj_e[t + 3];
        float s0 = g_dv[i0], s1 = g_dv[i1], s2 = g_dv[i2], s3 = g_dv[i3];
        float z00 = g_Z[i0 * COUT + lane], z01 = g_Z[i0 * COUT + lane + 32];
        float z10 = g_Z[i1 * COUT + lane], z11 = g_Z[i1 * COUT + lane + 32];
        float z20 = g_Z[i2 * COUT + lane], z21 = g_Z[i2 * COUT + lane + 32];
        float z30 = g_Z[i3 * COUT + lane], z31 = g_Z[i3 * COUT + lane + 32];
        a0 += (s0 * z00 + s1 * z10) + (s2 * z20 + s3 * z30);
        a1 += (s0 * z01 + s1 * z11) + (s2 * z21 + s3 * z31);
    }
    for (; t < end; t++) {
        int i0 = g_adj_e[t];
        float s0 = g_dv[i0];
        a0 += s0 * g_Z[i0 * COUT + lane];
        a1 += s0 * g_Z[i0 * COUT + lane + 32];
    }
    float de = g_de[w];
    g_Y2[w * COUT + lane]      = a0 * de;
    g_Y2[w * COUT + lane + 32] = a1 * de;
}

// ---------------- kernel 6: out = relu(dv .* (H @ Y2)) + counter reset ----------
__global__ void k_vertex(float* __restrict__ out) {
    int gt = blockIdx.x * blockDim.x + threadIdx.x;
    int w = gt >> 5;
    int lane = threadIdx.x & 31;
    if (w < N_V) {
        int t = g_off_v[w], end = g_off_v[w + 1];
        float a0 = 0.f, a1 = 0.f;
        for (; t + 4 <= end; t += 4) {
            int j0 = g_adj_v[t];
            int j1 = g_adj_v[t + 1];
            int j2 = g_adj_v[t + 2];
            int j3 = g_adj_v[t + 3];
            float y00 = g_Y2[j0 * COUT + lane], y01 = g_Y2[j0 * COUT + lane + 32];
            float y10 = g_Y2[j1 * COUT + lane], y11 = g_Y2[j1 * COUT + lane + 32];
            float y20 = g_Y2[j2 * COUT + lane], y21 = g_Y2[j2 * COUT + lane + 32];
            float y30 = g_Y2[j3 * COUT + lane], y31 = g_Y2[j3 * COUT + lane + 32];
            a0 += (y00 + y10) + (y20 + y30);
            a1 += (y01 + y11) + (y21 + y31);
        }
        for (; t < end; t++) {
            int j0 = g_adj_v[t];
            a0 += g_Y2[j0 * COUT + lane];
            a1 += g_Y2[j0 * COUT + lane + 32];
        }
        float dv = g_dv[w];
        float o0 = dv * a0;
        float o1 = dv * a1;
        out[w * COUT + lane]      = o0 > 0.f ? o0 : 0.f;
        out[w * COUT + lane + 32] = o1 > 0.f ? o1 : 0.f;
    }
    // tail: re-zero counters for the NEXT launch (stream-ordered; launch 0
    // covered by static zero-init of __device__ globals).
    if (gt < N_V) { g_deg_v[gt] = 0; g_cur_v[gt] = 0; }
    if (gt < N_E) { g_deg_e[gt] = 0; g_cur_e[gt] = 0; }
}

// ------ launch: extract -> [scan -> bucket || gemm] -> edge -> vertex ------
static cudaStream_t s2 = nullptr;
static cudaEvent_t  evFork = nullptr, evJoin = nullptr;

extern "C" void kernel_launch(void* const* d_in, const int* in_sizes, int n_in,
                              void* d_out, int out_size) {
    const float* X = (const float*)d_in[0];   // (16384, 128)
    const float* H = (const float*)d_in[1];   // (16384, 8192)
    const float* W = (const float*)d_in[2];   // (64, 128)
    const float* b = (const float*)d_in[3];   // (64,)
    float* out = (float*)d_out;               // (16384, 64)

    if (s2 == nullptr) {                      // one-time host init (first call is
        cudaStreamCreateWithFlags(&s2, cudaStreamNonBlocking);     // the uncaptured
        cudaEventCreateWithFlags(&evFork, cudaEventDisableTiming); // correctness run)
        cudaEventCreateWithFlags(&evJoin, cudaEventDisableTiming);
    }

    k_extract<<<EBLOCKS, ETHREADS>>>(H);

    // fork AFTER extract: gemm overlaps the low-issue scan+bucket window
    cudaEventRecord(evFork, 0);
    cudaStreamWaitEvent(s2, evFork, 0);
    k_gemm<<<N_V / 32, 128, 0, s2>>>(X, W, b);

    k_scan_scales<<<2, 1024>>>();
    k_bucket     <<<(EBLOCKS * CAPB) / 256, 256>>>();

    // join: k_edge needs Z (s2) and adjacency (main)
    cudaEventRecord(evJoin, s2);
    cudaStreamWaitEvent(0, evJoin, 0);

    k_edge  <<<(N_E * 32) / 256, 256>>>();
    k_vertex<<<(N_V * 32) / 256, 256>>>(out);
}